// round 13
// baseline (speedup 1.0000x reference)
#include <cuda_runtime.h>
#include <cuda_bf16.h>
#include <cstdint>

// ICPMatcher: exact NN via compact counting-sorted 48^3 grid, 4 launches.
//
//   k_count   (grid): atomicAdd into g_hist (zeroed by the PREVIOUS k_nn's
//                     prologue; static zero-init covers the first run)
//   k_scan    (1 CTA, 1024 thr): 108 cells/thread serial prefix + shfl block
//                     scan -> g_cellStart, g_cur
//   k_scatter (grid): compact counting-sort into g_sortedTgt
//   k_nn      (warp/source): prologue zeroes g_hist for the next replay;
//                     r<=1 cube scanned as 9 CONTIGUOUS point spans
//                     (lane-strided points: balanced + coalesced LDG.128);
//                     r>=2 shells cell-based with conservative prune
//                     ((r-1)h)^2 > bestD2 + margin.
//
// Exactness: superset cell coverage + identical fma distance chain +
// order-independent packed (monotone(d')|idx) u64-min -> decisions
// bit-identical to all passing rounds (expect rel_err 9.056796e-06).

typedef unsigned long long ull;

#define N_MAX   16384
#define G       48
#define NCELLS  (G * G * G)          // 110592 = 1024 * 108
#define CPT     108                  // cells per thread in k_scan
#define BBOX    6.0f
#define CELLH   0.25f
#define INVH    4.0f

static __device__ int    g_hist[NCELLS];          // zero-init at module load
static __device__ int    g_cellStart[NCELLS + 1];
static __device__ int    g_cur[NCELLS];
static __device__ float4 g_sortedTgt[N_MAX];      // (x,y,z, bitcast(origIdx))

static __device__ __forceinline__ unsigned int map_f32(float f) {
    unsigned int b = __float_as_uint(f);
    return (b & 0x80000000u) ? ~b : (b | 0x80000000u);
}
static __device__ __forceinline__ float unmap_f32(unsigned int m) {
    return __uint_as_float((m & 0x80000000u) ? (m ^ 0x80000000u) : ~m);
}
static __device__ __forceinline__ int clampi(int v, int lo, int hi) {
    return v < lo ? lo : (v > hi ? hi : v);
}
static __device__ __forceinline__ void cellOf(float x, float y, float z,
                                              int& cx, int& cy, int& cz) {
    cx = clampi((int)floorf((x + BBOX) * INVH), 0, G - 1);
    cy = clampi((int)floorf((y + BBOX) * INVH), 0, G - 1);
    cz = clampi((int)floorf((z + BBOX) * INVH), 0, G - 1);
}

// ---- preprocessing ---------------------------------------------------------

__global__ void k_count(const float* __restrict__ tgt, int n2) {
    int i = blockIdx.x * blockDim.x + threadIdx.x;
    if (i < n2) {
        int cx, cy, cz;
        cellOf(tgt[3 * i], tgt[3 * i + 1], tgt[3 * i + 2], cx, cy, cz);
        atomicAdd(&g_hist[(cz * G + cy) * G + cx], 1);
    }
}

__global__ __launch_bounds__(1024) void k_scan(int n2) {
    __shared__ int wsum[32];
    const int t = threadIdx.x;
    const int lane = t & 31;
    const int wid = t >> 5;
    const int base = t * CPT;

    int sum = 0;
    for (int k = 0; k < CPT; k++) sum += g_hist[base + k];

    int s = sum;
#pragma unroll
    for (int off = 1; off < 32; off <<= 1) {
        int o = __shfl_up_sync(0xFFFFFFFFu, s, off);
        if (lane >= off) s += o;
    }
    if (lane == 31) wsum[wid] = s;
    __syncthreads();
    if (wid == 0) {
        int ws = wsum[lane];
#pragma unroll
        for (int off = 1; off < 32; off <<= 1) {
            int o = __shfl_up_sync(0xFFFFFFFFu, ws, off);
            if (lane >= off) ws += o;
        }
        wsum[lane] = ws;
    }
    __syncthreads();
    int run = s - sum + (wid > 0 ? wsum[wid - 1] : 0);   // exclusive prefix

    for (int k = 0; k < CPT; k++) {
        const int v = g_hist[base + k];
        g_cellStart[base + k] = run;
        g_cur[base + k] = run;
        run += v;
    }
    if (t == 1023) g_cellStart[NCELLS] = n2;
}

__global__ void k_scatter(const float* __restrict__ tgt, int n2) {
    int i = blockIdx.x * blockDim.x + threadIdx.x;
    if (i < n2) {
        const float x = tgt[3 * i], y = tgt[3 * i + 1], z = tgt[3 * i + 2];
        int cx, cy, cz;
        cellOf(x, y, z, cx, cy, cz);
        const int pos = atomicAdd(&g_cur[(cz * G + cy) * G + cx], 1);
        g_sortedTgt[pos] = make_float4(x, y, z, __int_as_float(i));
    }
}

// ---- warp-cooperative NN search --------------------------------------------

__global__ __launch_bounds__(256) void k_nn(const float* __restrict__ src,
                                            float* __restrict__ out,
                                            int n1, int out_size) {
    // Zero g_hist for the next replay (grid has >= NCELLS threads).
    {
        const int gt = blockIdx.x * blockDim.x + threadIdx.x;
        for (int c = gt; c < NCELLS; c += gridDim.x * blockDim.x) g_hist[c] = 0;
    }

    const int warp = (blockIdx.x * blockDim.x + threadIdx.x) >> 5;
    const int lane = threadIdx.x & 31;
    if (warp >= n1) return;
    const int i = warp;

    const float x = src[3 * i], y = src[3 * i + 1], z = src[3 * i + 2];
    const float m2x = -2.f * x, m2y = -2.f * y, m2z = -2.f * z;
    const float s2 = fmaf(x, x, fmaf(y, y, z * z));

    int cx, cy, cz;
    cellOf(x, y, z, cx, cy, cz);

    ull best = 0xFFFFFFFFFFFFFFFFull;
    float bestD2 = __int_as_float(0x7f800000);

    // ---- r<=1: 3x3x3 cube as 9 contiguous point spans, lane-strided --------
    {
        const int x0 = max(cx - 1, 0), x1 = min(cx + 1, G - 1);
        ull lbest = best;
#pragma unroll
        for (int row = 0; row < 9; row++) {
            const int zz = cz + row / 3 - 1;
            const int yy = cy + row % 3 - 1;
            if (zz < 0 || zz >= G || yy < 0 || yy >= G) continue;
            const int cbase = (zz * G + yy) * G;
            const int p0 = __ldg(&g_cellStart[cbase + x0]);
            const int p1 = __ldg(&g_cellStart[cbase + x1 + 1]);
            for (int p = p0 + lane; p < p1; p += 32) {
                const float4 T = __ldg(&g_sortedTgt[p]);
                float t2 = fmaf(T.x, T.x, fmaf(T.y, T.y, T.z * T.z));
                float d  = fmaf(m2x, T.x, fmaf(m2y, T.y, fmaf(m2z, T.z, t2)));
                ull pk = ((ull)map_f32(d) << 32) |
                         (unsigned int)__float_as_int(T.w);
                if (pk < lbest) lbest = pk;
            }
        }
#pragma unroll
        for (int off = 16; off > 0; off >>= 1) {
            ull o = __shfl_xor_sync(0xFFFFFFFFu, lbest, off);
            if (o < lbest) lbest = o;
        }
        best = lbest;
        if (best != 0xFFFFFFFFFFFFFFFFull)
            bestD2 = unmap_f32((unsigned int)(best >> 32)) + s2;
    }

    // ---- r>=2 shells, cell-based -------------------------------------------
    for (int r = 2; r <= G; r++) {
        const float lb = (float)(r - 1) * CELLH;
        if (lb * lb > bestD2 + 1e-3f) break;

        const int side = 2 * r + 1;
        const int area = side * side;
        const int ncub = side * area;

        ull lbest = best;
        for (int t = lane; t < ncub; t += 32) {
            const int dz = t / area - r;
            const int rm = t % area;
            const int dy = rm / side - r;
            const int dx = rm % side - r;
            const int ch = max(abs(dx), max(abs(dy), abs(dz)));
            if (ch < r) continue;                // interior already scanned
            const int xx = cx + dx, yy = cy + dy, zz = cz + dz;
            if (xx < 0 || xx >= G || yy < 0 || yy >= G || zz < 0 || zz >= G)
                continue;
            const int c = (zz * G + yy) * G + xx;
            const int p0 = __ldg(&g_cellStart[c]);
            const int p1 = __ldg(&g_cellStart[c + 1]);
            for (int p = p0; p < p1; p++) {
                const float4 T = __ldg(&g_sortedTgt[p]);
                float t2 = fmaf(T.x, T.x, fmaf(T.y, T.y, T.z * T.z));
                float d  = fmaf(m2x, T.x, fmaf(m2y, T.y, fmaf(m2z, T.z, t2)));
                ull pk = ((ull)map_f32(d) << 32) |
                         (unsigned int)__float_as_int(T.w);
                if (pk < lbest) lbest = pk;
            }
        }
#pragma unroll
        for (int off = 16; off > 0; off >>= 1) {
            ull o = __shfl_xor_sync(0xFFFFFFFFu, lbest, off);
            if (o < lbest) lbest = o;
        }
        best = lbest;
        bestD2 = unmap_f32((unsigned int)(best >> 32)) + s2;
    }

    if (lane == 0) {
        const float dist = unmap_f32((unsigned int)(best >> 32)) + s2;
        const unsigned int idx = (unsigned int)(best & 0xFFFFFFFFu);
        if (i < out_size) out[i] = dist;
        if (n1 + i < out_size) out[n1 + i] = (float)idx;
    }
}

// ---- launch ----------------------------------------------------------------

extern "C" void kernel_launch(void* const* d_in, const int* in_sizes, int n_in,
                              void* d_out, int out_size) {
    const float* src = (const float*)d_in[0];
    const float* tgt = (const float*)d_in[1];
    const int n1 = in_sizes[0] / 3;
    const int n2 = in_sizes[1] / 3;
    float* out = (float*)d_out;

    k_count<<<(n2 + 255) / 256, 256>>>(tgt, n2);
    k_scan<<<1, 1024>>>(n2);
    k_scatter<<<(n2 + 255) / 256, 256>>>(tgt, n2);

    const int warps_per_cta = 256 / 32;
    k_nn<<<(n1 + warps_per_cta - 1) / warps_per_cta, 256>>>(src, out, n1, out_size);
}

// round 15
// speedup vs baseline: 5.9610x; 5.9610x over previous
#include <cuda_runtime.h>
#include <cuda_bf16.h>
#include <cstdint>

// ICPMatcher: exact NN via counting-sorted 32^3 grid, 5 launches.
// R8 (proven 55.6us) + two deltas:
//   - k_zero removed: g_hist zeroed in k_nn prologue (static init covers run 1)
//   - k_nn: home cell first, then ring-1 cells gated by an EXACT per-cell
//     box-distance bound (skip iff dmin^2 > bestD2 + 1e-3); survivors scanned
//     warp-cooperatively. Same bound inside r>=2 shells.
// Skipped cells are strictly farther than best+margin -> u64-min unchanged ->
// output bit-identical (expect rel_err 9.056796e-06 exactly).

typedef unsigned long long ull;

#define N_MAX   16384
#define G       32
#define NCELLS  (G * G * G)          // 32768
#define NBLK    (NCELLS / 1024)      // 32
#define BBOX    6.0f
#define CELLH   0.375f
#define INVH    2.6666667f

static __device__ int    g_hist[NCELLS];          // zero-init at module load
static __device__ int    g_bsum[NBLK];
static __device__ int    g_cellStart[NCELLS + 1];
static __device__ int    g_cur[NCELLS];
static __device__ float4 g_sortedTgt[N_MAX];      // (x,y,z, bitcast(origIdx))

static __device__ __forceinline__ unsigned int map_f32(float f) {
    unsigned int b = __float_as_uint(f);
    return (b & 0x80000000u) ? ~b : (b | 0x80000000u);
}
static __device__ __forceinline__ float unmap_f32(unsigned int m) {
    return __uint_as_float((m & 0x80000000u) ? (m ^ 0x80000000u) : ~m);
}
static __device__ __forceinline__ int clampi(int v, int lo, int hi) {
    return v < lo ? lo : (v > hi ? hi : v);
}
static __device__ __forceinline__ void cellOf(float x, float y, float z,
                                              int& cx, int& cy, int& cz) {
    cx = clampi((int)floorf((x + BBOX) * INVH), 0, G - 1);
    cy = clampi((int)floorf((y + BBOX) * INVH), 0, G - 1);
    cz = clampi((int)floorf((z + BBOX) * INVH), 0, G - 1);
}
// Exact min squared distance from point to cell (xx,yy,zz)'s box.
static __device__ __forceinline__ float cellMinDist2(float x, float y, float z,
                                                     int xx, int yy, int zz) {
    float lx = -BBOX + xx * CELLH, ly = -BBOX + yy * CELLH, lz = -BBOX + zz * CELLH;
    float dx = fmaxf(0.f, fmaxf(lx - x, x - (lx + CELLH)));
    float dy = fmaxf(0.f, fmaxf(ly - y, y - (ly + CELLH)));
    float dz = fmaxf(0.f, fmaxf(lz - z, z - (lz + CELLH)));
    return fmaf(dx, dx, fmaf(dy, dy, dz * dz));
}

// ---- preprocessing ---------------------------------------------------------

__global__ void k_count(const float* __restrict__ tgt, int n2) {
    int i = blockIdx.x * blockDim.x + threadIdx.x;
    if (i < n2) {
        int cx, cy, cz;
        cellOf(tgt[3 * i], tgt[3 * i + 1], tgt[3 * i + 2], cx, cy, cz);
        atomicAdd(&g_hist[(cz * G + cy) * G + cx], 1);
    }
}

// Level-1 exclusive scan in place (warp-shfl); block sums to g_bsum.
__global__ __launch_bounds__(1024) void k_scan1() {
    __shared__ int wsum[32];
    const int t = threadIdx.x;
    const int lane = t & 31;
    const int wid = t >> 5;
    const int g = blockIdx.x * 1024 + t;
    const int v = g_hist[g];

    int s = v;
#pragma unroll
    for (int off = 1; off < 32; off <<= 1) {
        int o = __shfl_up_sync(0xFFFFFFFFu, s, off);
        if (lane >= off) s += o;
    }
    if (lane == 31) wsum[wid] = s;
    __syncthreads();
    if (wid == 0) {
        int ws = wsum[lane];
#pragma unroll
        for (int off = 1; off < 32; off <<= 1) {
            int o = __shfl_up_sync(0xFFFFFFFFu, ws, off);
            if (lane >= off) ws += o;
        }
        wsum[lane] = ws;
    }
    __syncthreads();
    const int incl = s + (wid > 0 ? wsum[wid - 1] : 0);
    g_hist[g] = incl - v;
    if (t == 1023) g_bsum[blockIdx.x] = incl;
}

// Block-sum prefix (<=31 serial adds, L2-hot) + cellStart materialization.
__global__ __launch_bounds__(256) void k_scan23(int n2) {
    __shared__ int base;
    if (threadIdx.x == 0) {
        int acc = 0;
        const int lim = blockIdx.x >> 2;      // 1024-cell chunk index
        for (int k = 0; k < lim; k++) acc += g_bsum[k];
        base = acc;
    }
    __syncthreads();
    const int g = blockIdx.x * 256 + threadIdx.x;
    const int v = g_hist[g] + base;
    g_cellStart[g] = v;
    g_cur[g] = v;
    if (g == 0) g_cellStart[NCELLS] = n2;
}

__global__ void k_scatter(const float* __restrict__ tgt, int n2) {
    int i = blockIdx.x * blockDim.x + threadIdx.x;
    if (i < n2) {
        const float x = tgt[3 * i], y = tgt[3 * i + 1], z = tgt[3 * i + 2];
        int cx, cy, cz;
        cellOf(x, y, z, cx, cy, cz);
        const int pos = atomicAdd(&g_cur[(cz * G + cy) * G + cx], 1);
        g_sortedTgt[pos] = make_float4(x, y, z, __int_as_float(i));
    }
}

// ---- warp-cooperative NN search --------------------------------------------

static __device__ __forceinline__ ull scan_span(int p0, int p1, int lane,
                                                float m2x, float m2y, float m2z,
                                                ull lbest) {
    for (int p = p0 + lane; p < p1; p += 32) {
        const float4 T = __ldg(&g_sortedTgt[p]);
        float t2 = fmaf(T.x, T.x, fmaf(T.y, T.y, T.z * T.z));
        float d  = fmaf(m2x, T.x, fmaf(m2y, T.y, fmaf(m2z, T.z, t2)));
        ull pk = ((ull)map_f32(d) << 32) | (unsigned int)__float_as_int(T.w);
        if (pk < lbest) lbest = pk;
    }
    return lbest;
}
static __device__ __forceinline__ ull warp_min(ull v) {
#pragma unroll
    for (int off = 16; off > 0; off >>= 1) {
        ull o = __shfl_xor_sync(0xFFFFFFFFu, v, off);
        if (o < v) v = o;
    }
    return v;
}

__global__ __launch_bounds__(256) void k_nn(const float* __restrict__ src,
                                            float* __restrict__ out,
                                            int n1, int out_size) {
    // Zero g_hist for the next replay.
    {
        const int gt = blockIdx.x * blockDim.x + threadIdx.x;
        if (gt < NCELLS) g_hist[gt] = 0;
    }

    const int warp = (blockIdx.x * blockDim.x + threadIdx.x) >> 5;
    const int lane = threadIdx.x & 31;
    if (warp >= n1) return;
    const int i = warp;

    const float x = src[3 * i], y = src[3 * i + 1], z = src[3 * i + 2];
    const float m2x = -2.f * x, m2y = -2.f * y, m2z = -2.f * z;
    const float s2 = fmaf(x, x, fmaf(y, y, z * z));

    int cx, cy, cz;
    cellOf(x, y, z, cx, cy, cz);
    const int home = (cz * G + cy) * G + cx;

    ull best = 0xFFFFFFFFFFFFFFFFull;
    float bestD2 = __int_as_float(0x7f800000);

    // ---- pass A: home cell, lane-strided ----
    {
        const int p0 = __ldg(&g_cellStart[home]);
        const int p1 = __ldg(&g_cellStart[home + 1]);
        ull lbest = scan_span(p0, p1, lane, m2x, m2y, m2z, best);
        best = warp_min(lbest);
        if (best != 0xFFFFFFFFFFFFFFFFull)
            bestD2 = fmaxf(unmap_f32((unsigned int)(best >> 32)) + s2, 0.f);
    }

    // ---- pass B: ring-1 cells gated by exact per-cell bound ----
    {
        unsigned int survive = 0;
        if (lane < 27 && lane != 13) {
            const int dz = lane / 9 - 1, dy = (lane % 9) / 3 - 1, dx = lane % 3 - 1;
            const int xx = cx + dx, yy = cy + dy, zz = cz + dz;
            if (xx >= 0 && xx < G && yy >= 0 && yy < G && zz >= 0 && zz < G) {
                if (cellMinDist2(x, y, z, xx, yy, zz) <= bestD2 + 1e-3f)
                    survive = 1;
            }
        }
        unsigned int mask = __ballot_sync(0xFFFFFFFFu, survive);
        ull lbest = best;
        while (mask) {
            const int b = __ffs(mask) - 1;
            mask &= mask - 1;
            const int dz = b / 9 - 1, dy = (b % 9) / 3 - 1, dx = b % 3 - 1;
            const int c = ((cz + dz) * G + (cy + dy)) * G + (cx + dx);
            const int p0 = __ldg(&g_cellStart[c]);
            const int p1 = __ldg(&g_cellStart[c + 1]);
            lbest = scan_span(p0, p1, lane, m2x, m2y, m2z, lbest);
        }
        best = warp_min(lbest);
        if (best != 0xFFFFFFFFFFFFFFFFull)
            bestD2 = fmaxf(unmap_f32((unsigned int)(best >> 32)) + s2, 0.f);
    }

    // ---- pass C: r>=2 shells, cell-per-lane with per-cell bound ----
    for (int r = 2; r <= G; r++) {
        const float lb = (float)(r - 1) * CELLH;
        if (lb * lb > bestD2 + 1e-3f) break;

        const int side = 2 * r + 1;
        const int area = side * side;
        const int ncub = side * area;

        ull lbest = best;
        for (int t = lane; t < ncub; t += 32) {
            const int dz = t / area - r;
            const int rm = t % area;
            const int dy = rm / side - r;
            const int dx = rm % side - r;
            const int ch = max(abs(dx), max(abs(dy), abs(dz)));
            if (ch < r) continue;
            const int xx = cx + dx, yy = cy + dy, zz = cz + dz;
            if (xx < 0 || xx >= G || yy < 0 || yy >= G || zz < 0 || zz >= G)
                continue;
            if (cellMinDist2(x, y, z, xx, yy, zz) > bestD2 + 1e-3f) continue;
            const int c = (zz * G + yy) * G + xx;
            const int p0 = __ldg(&g_cellStart[c]);
            const int p1 = __ldg(&g_cellStart[c + 1]);
            for (int p = p0; p < p1; p++) {
                const float4 T = __ldg(&g_sortedTgt[p]);
                float t2 = fmaf(T.x, T.x, fmaf(T.y, T.y, T.z * T.z));
                float d  = fmaf(m2x, T.x, fmaf(m2y, T.y, fmaf(m2z, T.z, t2)));
                ull pk = ((ull)map_f32(d) << 32) |
                         (unsigned int)__float_as_int(T.w);
                if (pk < lbest) lbest = pk;
            }
        }
        best = warp_min(lbest);
        if (best != 0xFFFFFFFFFFFFFFFFull)
            bestD2 = fmaxf(unmap_f32((unsigned int)(best >> 32)) + s2, 0.f);
    }

    if (lane == 0) {
        const float dist = unmap_f32((unsigned int)(best >> 32)) + s2;
        const unsigned int idx = (unsigned int)(best & 0xFFFFFFFFu);
        if (i < out_size) out[i] = dist;
        if (n1 + i < out_size) out[n1 + i] = (float)idx;
    }
}

// ---- launch ----------------------------------------------------------------

extern "C" void kernel_launch(void* const* d_in, const int* in_sizes, int n_in,
                              void* d_out, int out_size) {
    const float* src = (const float*)d_in[0];
    const float* tgt = (const float*)d_in[1];
    const int n1 = in_sizes[0] / 3;
    const int n2 = in_sizes[1] / 3;
    float* out = (float*)d_out;

    k_count<<<(n2 + 255) / 256, 256>>>(tgt, n2);
    k_scan1<<<NBLK, 1024>>>();
    k_scan23<<<NCELLS / 256, 256>>>(n2);
    k_scatter<<<(n2 + 255) / 256, 256>>>(tgt, n2);

    const int warps_per_cta = 256 / 32;
    k_nn<<<(n1 + warps_per_cta - 1) / warps_per_cta, 256>>>(src, out, n1, out_size);
}